// round 2
// baseline (speedup 1.0000x reference)
#include <cuda_runtime.h>

#define N_NODES 10000
#define N_EDGES 640000
#define D 128
#define TILE_NODES 16

// Scratch (allocation-free rule: __device__ globals)
__device__ float g_agg[N_NODES * D];
__device__ float g_deg[N_NODES];

// ---------------------------------------------------------------------------
// K1: zero the accumulators
// ---------------------------------------------------------------------------
__global__ void zero_kernel() {
    int i = blockIdx.x * blockDim.x + threadIdx.x;
    int stride = gridDim.x * blockDim.x;
    for (int idx = i; idx < N_NODES * D; idx += stride)
        g_agg[idx] = 0.0f;
    for (int idx = i; idx < N_NODES; idx += stride)
        g_deg[idx] = 0.0f;
}

// ---------------------------------------------------------------------------
// K2: one warp per edge. Gather sender row (float4 per lane), scatter-add
// into receiver row with scalar float atomics. Degree bump from lane 0.
// ---------------------------------------------------------------------------
__global__ void __launch_bounds__(256) scatter_kernel(
    const float* __restrict__ nodes,
    const int* __restrict__ senders,
    const int* __restrict__ receivers)
{
    int warp_id = (blockIdx.x * blockDim.x + threadIdx.x) >> 5;
    int lane = threadIdx.x & 31;
    if (warp_id >= N_EDGES) return;

    int s = __ldg(senders + warp_id);
    int r = __ldg(receivers + warp_id);

    const float4* src = reinterpret_cast<const float4*>(nodes + (size_t)s * D);
    float4 v = __ldg(src + lane);   // 32 lanes x float4 = 128 floats

    float* dst = g_agg + (size_t)r * D + lane * 4;
    atomicAdd(dst + 0, v.x);
    atomicAdd(dst + 1, v.y);
    atomicAdd(dst + 2, v.z);
    atomicAdd(dst + 3, v.w);

    if (lane == 0) atomicAdd(&g_deg[r], 1.0f);
}

// ---------------------------------------------------------------------------
// K3: degree-normalize + GEMM (agg/deg) @ W + b.
// Block = 128 threads, TILE_NODES nodes per block.
// A-tile (normalized) lives in static shared; W read through L1/L2 (__ldg),
// coalesced across the 32-lane j dimension and fully L1-resident after the
// first pass (64 KB).
// ---------------------------------------------------------------------------
__global__ void __launch_bounds__(128) proj_kernel(
    const float* __restrict__ W,
    const float* __restrict__ b,
    float* __restrict__ out)
{
    __shared__ float As[TILE_NODES * D];   // 8 KB

    int tid = threadIdx.x;
    int node0 = blockIdx.x * TILE_NODES;

    // Load + normalize the A tile
    for (int i = tid; i < TILE_NODES * (D / 4); i += 128) {
        int n  = i / (D / 4);
        int k4 = i % (D / 4);
        float invd = 1.0f / fmaxf(g_deg[node0 + n], 1.0f);
        float4 v = reinterpret_cast<const float4*>(g_agg + (size_t)(node0 + n) * D)[k4];
        v.x *= invd; v.y *= invd; v.z *= invd; v.w *= invd;
        reinterpret_cast<float4*>(As)[i] = v;
    }
    __syncthreads();

    int j = tid;  // output column
    float acc[TILE_NODES];
    #pragma unroll
    for (int i = 0; i < TILE_NODES; i++) acc[i] = 0.0f;

    #pragma unroll 4
    for (int k = 0; k < D; k++) {
        float w = __ldg(W + k * D + j);
        #pragma unroll
        for (int i = 0; i < TILE_NODES; i++)
            acc[i] += As[i * D + k] * w;
    }

    float bj = __ldg(b + j);
    #pragma unroll
    for (int i = 0; i < TILE_NODES; i++)
        out[(size_t)(node0 + i) * D + j] = acc[i] + bj;
}

// ---------------------------------------------------------------------------
// Launch
// ---------------------------------------------------------------------------
extern "C" void kernel_launch(void* const* d_in, const int* in_sizes, int n_in,
                              void* d_out, int out_size) {
    const float* nodes     = (const float*)d_in[0];
    const int*   senders   = (const int*)d_in[1];
    const int*   receivers = (const int*)d_in[2];
    const float* W         = (const float*)d_in[3];
    const float* b         = (const float*)d_in[4];
    float* out = (float*)d_out;

    zero_kernel<<<1024, 256>>>();

    // one warp per edge: E warps = E*32 threads, 256 threads/block
    int scatter_blocks = (N_EDGES * 32) / 256;   // 80000
    scatter_kernel<<<scatter_blocks, 256>>>(nodes, senders, receivers);

    proj_kernel<<<N_NODES / TILE_NODES, 128>>>(W, b, out);
}

// round 3
// speedup vs baseline: 2.2701x; 2.2701x over previous
#include <cuda_runtime.h>

#define N_NODES 10000
#define N_EDGES 640000
#define D 128
#define TILE_NODES 16

// Scratch (allocation-free rule: __device__ globals)
__device__ float g_agg[N_NODES * D];
__device__ float g_deg[N_NODES];

// ---------------------------------------------------------------------------
// K1: zero the accumulators
// ---------------------------------------------------------------------------
__global__ void zero_kernel() {
    int i = blockIdx.x * blockDim.x + threadIdx.x;
    int stride = gridDim.x * blockDim.x;
    for (int idx = i; idx < N_NODES * D; idx += stride)
        g_agg[idx] = 0.0f;
    for (int idx = i; idx < N_NODES; idx += stride)
        g_deg[idx] = 0.0f;
}

// ---------------------------------------------------------------------------
// K2: one warp per edge. Gather sender row (float4 per lane), scatter-add
// into receiver row with ONE vector reduction per lane (red.global.add.v4.f32
// -> RED.128), quartering atomic issue count vs scalar atomicAdd.
// ---------------------------------------------------------------------------
__device__ __forceinline__ void red_add_v4(float* addr, float4 v) {
    asm volatile("red.global.add.v4.f32 [%0], {%1, %2, %3, %4};"
                 :: "l"(addr), "f"(v.x), "f"(v.y), "f"(v.z), "f"(v.w)
                 : "memory");
}

__global__ void __launch_bounds__(256) scatter_kernel(
    const float* __restrict__ nodes,
    const int* __restrict__ senders,
    const int* __restrict__ receivers)
{
    int warp_id = (blockIdx.x * blockDim.x + threadIdx.x) >> 5;
    int lane = threadIdx.x & 31;
    if (warp_id >= N_EDGES) return;

    int s = __ldg(senders + warp_id);
    int r = __ldg(receivers + warp_id);

    const float4* src = reinterpret_cast<const float4*>(nodes + (size_t)s * D);
    float4 v = __ldg(src + lane);   // 32 lanes x float4 = 128 floats

    float* dst = g_agg + (size_t)r * D + lane * 4;
    red_add_v4(dst, v);

    if (lane == 0) atomicAdd(&g_deg[r], 1.0f);
}

// ---------------------------------------------------------------------------
// K3: degree-normalize + GEMM (agg/deg) @ W + b.
// Block = 128 threads, TILE_NODES nodes per block.
// ---------------------------------------------------------------------------
__global__ void __launch_bounds__(128) proj_kernel(
    const float* __restrict__ W,
    const float* __restrict__ b,
    float* __restrict__ out)
{
    __shared__ float As[TILE_NODES * D];   // 8 KB

    int tid = threadIdx.x;
    int node0 = blockIdx.x * TILE_NODES;

    // Load + normalize the A tile
    for (int i = tid; i < TILE_NODES * (D / 4); i += 128) {
        int n  = i / (D / 4);
        int k4 = i % (D / 4);
        float invd = 1.0f / fmaxf(g_deg[node0 + n], 1.0f);
        float4 v = reinterpret_cast<const float4*>(g_agg + (size_t)(node0 + n) * D)[k4];
        v.x *= invd; v.y *= invd; v.z *= invd; v.w *= invd;
        reinterpret_cast<float4*>(As)[i] = v;
    }
    __syncthreads();

    int j = tid;  // output column
    float acc[TILE_NODES];
    #pragma unroll
    for (int i = 0; i < TILE_NODES; i++) acc[i] = 0.0f;

    #pragma unroll 4
    for (int k = 0; k < D; k++) {
        float w = __ldg(W + k * D + j);
        #pragma unroll
        for (int i = 0; i < TILE_NODES; i++)
            acc[i] += As[i * D + k] * w;
    }

    float bj = __ldg(b + j);
    #pragma unroll
    for (int i = 0; i < TILE_NODES; i++)
        out[(size_t)(node0 + i) * D + j] = acc[i] + bj;
}

// ---------------------------------------------------------------------------
// Launch
// ---------------------------------------------------------------------------
extern "C" void kernel_launch(void* const* d_in, const int* in_sizes, int n_in,
                              void* d_out, int out_size) {
    const float* nodes     = (const float*)d_in[0];
    const int*   senders   = (const int*)d_in[1];
    const int*   receivers = (const int*)d_in[2];
    const float* W         = (const float*)d_in[3];
    const float* b         = (const float*)d_in[4];
    float* out = (float*)d_out;

    zero_kernel<<<1024, 256>>>();

    // one warp per edge: E warps = E*32 threads, 256 threads/block
    int scatter_blocks = (N_EDGES * 32) / 256;   // 80000
    scatter_kernel<<<scatter_blocks, 256>>>(nodes, senders, receivers);

    proj_kernel<<<N_NODES / TILE_NODES, 128>>>(W, b, out);
}

// round 5
// speedup vs baseline: 2.3767x; 1.0470x over previous
#include <cuda_runtime.h>

#define N_NODES 10000
#define N_EDGES 640000
#define D 128
#define TILE_NODES 16
#define NODES_PER_BLOCK 8   // accumulate: 8 warps/block, 1 node per warp

// Scratch (allocation-free rule: __device__ globals)
__device__ float g_agg[N_NODES * D];     // normalized aggregate, written once
__device__ int   g_count[N_NODES];       // in-degree
__device__ int   g_off[N_NODES];         // CSR row offsets (exclusive scan)
__device__ int   g_cursor[N_NODES];      // mutable copy for edge placement
__device__ int   g_ss[N_EDGES];          // sender ids, grouped by receiver

// ---------------------------------------------------------------------------
// K1: zero the degree counters (g_agg is fully overwritten; no zeroing needed)
// ---------------------------------------------------------------------------
__global__ void zero_count_kernel() {
    int i = blockIdx.x * blockDim.x + threadIdx.x;
    if (i < N_NODES) g_count[i] = 0;
}

// ---------------------------------------------------------------------------
// K2: histogram of receivers
// ---------------------------------------------------------------------------
__global__ void __launch_bounds__(256) hist_kernel(const int* __restrict__ receivers) {
    int e = blockIdx.x * blockDim.x + threadIdx.x;
    if (e < N_EDGES) atomicAdd(&g_count[receivers[e]], 1);
}

// ---------------------------------------------------------------------------
// K3: single-block exclusive prefix scan of g_count -> g_off / g_cursor
// ---------------------------------------------------------------------------
__global__ void __launch_bounds__(1024) scan_kernel() {
    __shared__ int sdata[1024];
    int carry = 0;
    for (int base = 0; base < N_NODES; base += 1024) {
        int i = base + threadIdx.x;
        int v = (i < N_NODES) ? g_count[i] : 0;
        sdata[threadIdx.x] = v;
        __syncthreads();
        #pragma unroll
        for (int off = 1; off < 1024; off <<= 1) {
            int t = (threadIdx.x >= off) ? sdata[threadIdx.x - off] : 0;
            __syncthreads();
            sdata[threadIdx.x] += t;
            __syncthreads();
        }
        int excl = sdata[threadIdx.x] - v;
        if (i < N_NODES) {
            g_off[i]    = carry + excl;
            g_cursor[i] = carry + excl;
        }
        int total = sdata[1023];
        __syncthreads();
        carry += total;
    }
}

// ---------------------------------------------------------------------------
// K4: place sender ids grouped by receiver (CSR build)
// ---------------------------------------------------------------------------
__global__ void __launch_bounds__(256) place_kernel(
    const int* __restrict__ senders, const int* __restrict__ receivers) {
    int e = blockIdx.x * blockDim.x + threadIdx.x;
    if (e >= N_EDGES) return;
    int r = receivers[e];
    int pos = atomicAdd(&g_cursor[r], 1);
    g_ss[pos] = senders[e];
}

// ---------------------------------------------------------------------------
// K5: one warp per receiver node. Gather all sender rows (float4 per lane),
// accumulate in registers (unroll-4 for MLP), normalize, write row ONCE.
// ---------------------------------------------------------------------------
__global__ void __launch_bounds__(NODES_PER_BLOCK * 32) accum_kernel(
    const float* __restrict__ nodes) {
    int warp = threadIdx.x >> 5;
    int lane = threadIdx.x & 31;
    int node = blockIdx.x * NODES_PER_BLOCK + warp;
    if (node >= N_NODES) return;

    int beg = g_off[node];
    int cnt = g_count[node];

    const float4* nodes4 = reinterpret_cast<const float4*>(nodes);
    float4 acc = make_float4(0.f, 0.f, 0.f, 0.f);

    int i = 0;
    for (; i + 4 <= cnt; i += 4) {
        int s0 = __ldg(g_ss + beg + i + 0);
        int s1 = __ldg(g_ss + beg + i + 1);
        int s2 = __ldg(g_ss + beg + i + 2);
        int s3 = __ldg(g_ss + beg + i + 3);
        float4 v0 = __ldg(nodes4 + (size_t)s0 * 32 + lane);
        float4 v1 = __ldg(nodes4 + (size_t)s1 * 32 + lane);
        float4 v2 = __ldg(nodes4 + (size_t)s2 * 32 + lane);
        float4 v3 = __ldg(nodes4 + (size_t)s3 * 32 + lane);
        acc.x += v0.x + v1.x + v2.x + v3.x;
        acc.y += v0.y + v1.y + v2.y + v3.y;
        acc.z += v0.z + v1.z + v2.z + v3.z;
        acc.w += v0.w + v1.w + v2.w + v3.w;
    }
    for (; i < cnt; i++) {
        int s = __ldg(g_ss + beg + i);
        float4 v = __ldg(nodes4 + (size_t)s * 32 + lane);
        acc.x += v.x; acc.y += v.y; acc.z += v.z; acc.w += v.w;
    }

    float invd = 1.0f / fmaxf((float)cnt, 1.0f);
    acc.x *= invd; acc.y *= invd; acc.z *= invd; acc.w *= invd;
    reinterpret_cast<float4*>(g_agg)[(size_t)node * 32 + lane] = acc;
}

// ---------------------------------------------------------------------------
// K6: GEMM  g_agg @ W + b
// ---------------------------------------------------------------------------
__global__ void __launch_bounds__(128) proj_kernel(
    const float* __restrict__ W,
    const float* __restrict__ b,
    float* __restrict__ out)
{
    __shared__ float As[TILE_NODES * D];   // 8 KB

    int tid = threadIdx.x;
    int node0 = blockIdx.x * TILE_NODES;

    for (int i = tid; i < TILE_NODES * (D / 4); i += 128) {
        reinterpret_cast<float4*>(As)[i] =
            reinterpret_cast<const float4*>(g_agg + (size_t)node0 * D)[i];
    }
    __syncthreads();

    int j = tid;
    float acc[TILE_NODES];
    #pragma unroll
    for (int i = 0; i < TILE_NODES; i++) acc[i] = 0.0f;

    #pragma unroll 4
    for (int k = 0; k < D; k++) {
        float w = __ldg(W + k * D + j);
        #pragma unroll
        for (int i = 0; i < TILE_NODES; i++)
            acc[i] += As[i * D + k] * w;
    }

    float bj = __ldg(b + j);
    #pragma unroll
    for (int i = 0; i < TILE_NODES; i++)
        out[(size_t)(node0 + i) * D + j] = acc[i] + bj;
}

// ---------------------------------------------------------------------------
// Launch
// ---------------------------------------------------------------------------
extern "C" void kernel_launch(void* const* d_in, const int* in_sizes, int n_in,
                              void* d_out, int out_size) {
    const float* nodes     = (const float*)d_in[0];
    const int*   senders   = (const int*)d_in[1];
    const int*   receivers = (const int*)d_in[2];
    const float* W         = (const float*)d_in[3];
    const float* b         = (const float*)d_in[4];
    float* out = (float*)d_out;

    zero_count_kernel<<<(N_NODES + 255) / 256, 256>>>();
    hist_kernel<<<(N_EDGES + 255) / 256, 256>>>(receivers);
    scan_kernel<<<1, 1024>>>();
    place_kernel<<<(N_EDGES + 255) / 256, 256>>>(senders, receivers);
    accum_kernel<<<(N_NODES + NODES_PER_BLOCK - 1) / NODES_PER_BLOCK,
                   NODES_PER_BLOCK * 32>>>(nodes);
    proj_kernel<<<N_NODES / TILE_NODES, 128>>>(W, b, out);
}